// round 15
// baseline (speedup 1.0000x reference)
#include <cuda_runtime.h>
#include <cuda_fp16.h>
#include <stdint.h>
#include <math.h>

// ----------------------------------------------------------------------------
// FARGAN vocoder. Round 14: R13 base (4-CTA clusters, 2 rows/cluster, 128
// CTAs, HH-hoisted phase A) + redundant small stages: fwglu/GLU1-3/skipglu
// computed full-width in every CTA (weights un-sliced) -> their DSMEM
// exchanges and cluster syncs vanish (11 -> 6 syncs/subframe).
// fp16 K-major weights, fp32 accumulate.
// ----------------------------------------------------------------------------

#define NFRAMES 100
#define NB      64
#define NTHREADS 1024

__device__ __forceinline__ float sigmoidf_(float x) { return 1.0f / (1.0f + expf(-x)); }

__device__ __forceinline__ uint32_t s2u_(const void* p) {
  uint32_t a;
  asm("{ .reg .u64 t; cvta.to.shared.u64 t, %1; cvt.u32.u64 %0, t; }" : "=r"(a) : "l"(p));
  return a;
}
__device__ __forceinline__ uint32_t mapa_u_(uint32_t a, uint32_t r) {
  uint32_t d;
  asm("mapa.shared::cluster.u32 %0, %1, %2;" : "=r"(d) : "r"(a), "r"(r));
  return d;
}
__device__ __forceinline__ void st_peer_(uint32_t a, float v) {
  asm volatile("st.shared::cluster.f32 [%0], %1;" :: "r"(a), "f"(v));
}
#define CLUSTER_SYNC_() do { \
  asm volatile("barrier.cluster.arrive.aligned;" ::: "memory"); \
  asm volatile("barrier.cluster.wait.aligned;" ::: "memory"); \
} while (0)

// fp16 weights. Rank-sliced matrices: [4][Kpad][Oq]. Full matrices (fwglu,
// glu1-3, skipglu): [K][256] un-sliced.
enum : int {
  OFFH_FW      = 0,                          // 4 x 544 x 64
  OFFH_FWGLU   = OFFH_FW      + 544 * 256,   // 256 x 256 FULL
  OFFH_G1IH    = OFFH_FWGLU   + 256 * 256,   // 4 x 384 x 192
  OFFH_G1HH    = OFFH_G1IH    + 384 * 768,   // 4 x 256 x 192
  OFFH_G2IH    = OFFH_G1HH    + 256 * 768,
  OFFH_G2HH    = OFFH_G2IH    + 384 * 768,
  OFFH_G3IH    = OFFH_G2HH    + 256 * 768,
  OFFH_G3HH    = OFFH_G3IH    + 384 * 768,
  OFFH_GLU1    = OFFH_G3HH    + 256 * 768,   // 256 x 256 FULL
  OFFH_GLU2    = OFFH_GLU1    + 256 * 256,
  OFFH_GLU3    = OFFH_GLU2    + 256 * 256,
  OFFH_SKIP    = OFFH_GLU3    + 256 * 256,   // 4 x 1152 x 64
  OFFH_SKIPGLU = OFFH_SKIP    + 1152 * 256,  // 256 x 256 FULL
  WH_TOTAL     = OFFH_SKIPGLU + 256 * 256
};

enum : int {
  OFFC_C1  = 0,
  OFFC_C2  = OFFC_C1 + 336 * 336,
  OFFC_C3  = OFFC_C2 + 336 * 336,
  WC_TOTAL = OFFC_C3 + 336 * 512
};

__device__ __half g_wh[WH_TOTAL];
__device__ float  g_wc[WC_TOTAL];
__device__ float  g_cond[NFRAMES * NB * 512];

// ---------------------------------------------------------------------------
__global__ void transpose_k(const float* __restrict__ src, float* __restrict__ dst,
                            int O, int I) {
  int idx = blockIdx.x * blockDim.x + threadIdx.x;
  if (idx < O * I) {
    int i = idx / O;
    int o = idx % O;
    dst[idx] = src[o * I + i];
  }
}

// 4-way mode0 reorg: src[O][I] -> dst[4][Ipad][O/4] fp16
__global__ void reorg_h4(const float* __restrict__ src, __half* __restrict__ dst,
                         int O, int I, int Ipad) {
  int idx = blockIdx.x * blockDim.x + threadIdx.x;
  if (idx >= O * Ipad) return;
  int i = idx / O, o = idx % O;
  int Oq = O >> 2;
  int r = o / Oq, c = o % Oq;
  float v = (i < I) ? src[o * I + i] : 0.f;
  dst[((size_t)r * Ipad + i) * Oq + c] = __float2half(v);
}

// full transpose -> fp16 K-major [I][O]
__global__ void reorg_full(const float* __restrict__ src, __half* __restrict__ dst,
                           int O, int I) {
  int idx = blockIdx.x * blockDim.x + threadIdx.x;
  if (idx >= O * I) return;
  int i = idx / O, o = idx % O;
  dst[(size_t)i * O + o] = __float2half(src[o * I + i]);
}

// 4-way GRU reorg (gate-permuted): w[768][I] -> dst[4][I][192]
__global__ void reorg_gru4(const float* __restrict__ src, __half* __restrict__ dst,
                           int I) {
  int idx = blockIdx.x * blockDim.x + threadIdx.x;
  if (idx >= 768 * I) return;
  int i = idx / 768, o = idx % 768;
  int s = o & 255, g = o >> 8;
  int r = s >> 6, c = g * 64 + (s & 63);
  dst[((size_t)r * I + i) * 192 + c] = __float2half(src[o * I + i]);
}

// ---------------------------------------------------------------------------
// 2-row fp16 GEMV partial, all 32 warps = 32 K-chunks x 32 lanes.
template <int K, int NQ>
__device__ __forceinline__ void gemv2r(const __half* __restrict__ Wh,
                                       const float* __restrict__ xs, int rs,
                                       float* __restrict__ part) {
  const int tid  = threadIdx.x;
  const int kc   = tid >> 5;
  const int lane = tid & 31;
  constexpr int Kc  = K / 32;
  constexpr int NV2 = NQ / 4;
  const float2* __restrict__ W2 =
      reinterpret_cast<const float2*>(Wh) + (size_t)(kc * Kc) * NV2;

  if (NQ == 64) {
    const int row = lane >> 4, v = lane & 15;
    const float* xk = xs + row * rs + kc * Kc;
    float acc[4] = {0.f, 0.f, 0.f, 0.f};
#pragma unroll 8
    for (int k = 0; k < Kc; ++k) {
      const float xv = xk[k];
      float2 hw = W2[k * 16 + v];
      const __half2* hp = reinterpret_cast<const __half2*>(&hw);
      float2 f0 = __half22float2(hp[0]);
      float2 f1 = __half22float2(hp[1]);
      acc[0] = fmaf(xv, f0.x, acc[0]);
      acc[1] = fmaf(xv, f0.y, acc[1]);
      acc[2] = fmaf(xv, f1.x, acc[2]);
      acc[3] = fmaf(xv, f1.y, acc[3]);
    }
    float4* P4 = reinterpret_cast<float4*>(part + (row * 32 + kc) * 64);
    P4[v] = make_float4(acc[0], acc[1], acc[2], acc[3]);
  } else if (NQ == 192) {
    const float* xk0 = xs + kc * Kc;
    const float* xk1 = xs + rs + kc * Kc;
    float a0[2][4], a1[2][4];
#pragma unroll
    for (int j = 0; j < 4; ++j) { a0[0][j] = a0[1][j] = a1[0][j] = a1[1][j] = 0.f; }
#pragma unroll
    for (int k = 0; k < Kc; ++k) {
      const float x0 = xk0[k], x1 = xk1[k];
      float2 hwa = W2[k * 48 + lane];
      const __half2* hpa = reinterpret_cast<const __half2*>(&hwa);
      float2 fa0 = __half22float2(hpa[0]);
      float2 fa1 = __half22float2(hpa[1]);
      a0[0][0] = fmaf(x0, fa0.x, a0[0][0]); a0[0][1] = fmaf(x0, fa0.y, a0[0][1]);
      a0[0][2] = fmaf(x0, fa1.x, a0[0][2]); a0[0][3] = fmaf(x0, fa1.y, a0[0][3]);
      a0[1][0] = fmaf(x1, fa0.x, a0[1][0]); a0[1][1] = fmaf(x1, fa0.y, a0[1][1]);
      a0[1][2] = fmaf(x1, fa1.x, a0[1][2]); a0[1][3] = fmaf(x1, fa1.y, a0[1][3]);
      if (lane < 16) {
        float2 hwb = W2[k * 48 + 32 + lane];
        const __half2* hpb = reinterpret_cast<const __half2*>(&hwb);
        float2 fb0 = __half22float2(hpb[0]);
        float2 fb1 = __half22float2(hpb[1]);
        a1[0][0] = fmaf(x0, fb0.x, a1[0][0]); a1[0][1] = fmaf(x0, fb0.y, a1[0][1]);
        a1[0][2] = fmaf(x0, fb1.x, a1[0][2]); a1[0][3] = fmaf(x0, fb1.y, a1[0][3]);
        a1[1][0] = fmaf(x1, fb0.x, a1[1][0]); a1[1][1] = fmaf(x1, fb0.y, a1[1][1]);
        a1[1][2] = fmaf(x1, fb1.x, a1[1][2]); a1[1][3] = fmaf(x1, fb1.y, a1[1][3]);
      }
    }
#pragma unroll
    for (int row = 0; row < 2; ++row) {
      float4* P4 = reinterpret_cast<float4*>(part + (row * 32 + kc) * 192);
      P4[lane] = make_float4(a0[row][0], a0[row][1], a0[row][2], a0[row][3]);
      if (lane < 16)
        P4[32 + lane] = make_float4(a1[row][0], a1[row][1], a1[row][2], a1[row][3]);
    }
  } else {  // NQ == 256 (full width, redundant stages)
    const float* xk0 = xs + kc * Kc;
    const float* xk1 = xs + rs + kc * Kc;
    float a0[2][4], a1[2][4];
#pragma unroll
    for (int j = 0; j < 4; ++j) { a0[0][j] = a0[1][j] = a1[0][j] = a1[1][j] = 0.f; }
#pragma unroll
    for (int k = 0; k < Kc; ++k) {
      const float x0 = xk0[k], x1 = xk1[k];
      float2 hwa = W2[k * 64 + lane];
      float2 hwb = W2[k * 64 + 32 + lane];
      const __half2* hpa = reinterpret_cast<const __half2*>(&hwa);
      const __half2* hpb = reinterpret_cast<const __half2*>(&hwb);
      float2 fa0 = __half22float2(hpa[0]);
      float2 fa1 = __half22float2(hpa[1]);
      float2 fb0 = __half22float2(hpb[0]);
      float2 fb1 = __half22float2(hpb[1]);
      a0[0][0] = fmaf(x0, fa0.x, a0[0][0]); a0[0][1] = fmaf(x0, fa0.y, a0[0][1]);
      a0[0][2] = fmaf(x0, fa1.x, a0[0][2]); a0[0][3] = fmaf(x0, fa1.y, a0[0][3]);
      a0[1][0] = fmaf(x1, fa0.x, a0[1][0]); a0[1][1] = fmaf(x1, fa0.y, a0[1][1]);
      a0[1][2] = fmaf(x1, fa1.x, a0[1][2]); a0[1][3] = fmaf(x1, fa1.y, a0[1][3]);
      a1[0][0] = fmaf(x0, fb0.x, a1[0][0]); a1[0][1] = fmaf(x0, fb0.y, a1[0][1]);
      a1[0][2] = fmaf(x0, fb1.x, a1[0][2]); a1[0][3] = fmaf(x0, fb1.y, a1[0][3]);
      a1[1][0] = fmaf(x1, fb0.x, a1[1][0]); a1[1][1] = fmaf(x1, fb0.y, a1[1][1]);
      a1[1][2] = fmaf(x1, fb1.x, a1[1][2]); a1[1][3] = fmaf(x1, fb1.y, a1[1][3]);
    }
#pragma unroll
    for (int row = 0; row < 2; ++row) {
      float4* P4 = reinterpret_cast<float4*>(part + (row * 32 + kc) * 256);
      P4[lane]      = make_float4(a0[row][0], a0[row][1], a0[row][2], a0[row][3]);
      P4[32 + lane] = make_float4(a1[row][0], a1[row][1], a1[row][2], a1[row][3]);
    }
  }
}

__device__ __forceinline__ float csum2r(const float* __restrict__ part, int NQ,
                                        int row, int j) {
  const float* p = part + (row * 32) * NQ + j;
  float s = 0.f;
#pragma unroll
  for (int c = 0; c < 32; c += 4) {
    float a = p[c * NQ]       + p[(c + 1) * NQ];
    float b = p[(c + 2) * NQ] + p[(c + 3) * NQ];
    s += (a + b);
  }
  return s;
}

// ---------------------------------------------------------------------------
// Phase-A gemvs on 8-warp groups (as R13).
__device__ __forceinline__ void gemv_fw8(const __half* __restrict__ Wh,
                                         const float* __restrict__ xs, int rs,
                                         float* __restrict__ part) {
  const int w = threadIdx.x >> 5;
  const int lane = threadIdx.x & 31;
  const int row = lane >> 4, v = lane & 15;
  constexpr int Kc = 544 / 8;
  const float* xk = xs + row * rs + w * Kc;
  const float2* __restrict__ W2 =
      reinterpret_cast<const float2*>(Wh) + (size_t)(w * Kc) * 16 + v;
  float acc[4] = {0.f, 0.f, 0.f, 0.f};
#pragma unroll 8
  for (int k = 0; k < Kc; ++k) {
    const float xv = xk[k];
    float2 hw = W2[k * 16];
    const __half2* hp = reinterpret_cast<const __half2*>(&hw);
    float2 f0 = __half22float2(hp[0]);
    float2 f1 = __half22float2(hp[1]);
    acc[0] = fmaf(xv, f0.x, acc[0]);
    acc[1] = fmaf(xv, f0.y, acc[1]);
    acc[2] = fmaf(xv, f1.x, acc[2]);
    acc[3] = fmaf(xv, f1.y, acc[3]);
  }
  reinterpret_cast<float4*>(part + (row * 8 + w) * 64)[v] =
      make_float4(acc[0], acc[1], acc[2], acc[3]);
}

__device__ __forceinline__ float csum_fw8(const float* __restrict__ p,
                                          int row, int j) {
  const float* q = p + row * 8 * 64 + j;
  float a = q[0]       + q[64];
  float b = q[2 * 64]  + q[3 * 64];
  float c = q[4 * 64]  + q[5 * 64];
  float d = q[6 * 64]  + q[7 * 64];
  return (a + b) + (c + d);
}

__device__ __forceinline__ void gemv_hh8(const __half* __restrict__ Wh,
                                         const float* __restrict__ xs,
                                         float* __restrict__ part) {
  const int wg = (threadIdx.x >> 5) & 7;
  const int lane = threadIdx.x & 31;
  constexpr int Kc = 32;
  const float* xk0 = xs + wg * Kc;
  const float* xk1 = xs + 256 + wg * Kc;
  const float2* __restrict__ W2 =
      reinterpret_cast<const float2*>(Wh) + (size_t)(wg * Kc) * 48;

  float a0[2][4], a1[2][4];
#pragma unroll
  for (int j = 0; j < 4; ++j) { a0[0][j] = a0[1][j] = a1[0][j] = a1[1][j] = 0.f; }
#pragma unroll 4
  for (int k = 0; k < Kc; ++k) {
    const float x0 = xk0[k], x1 = xk1[k];
    float2 hwa = W2[k * 48 + lane];
    const __half2* hpa = reinterpret_cast<const __half2*>(&hwa);
    float2 fa0 = __half22float2(hpa[0]);
    float2 fa1 = __half22float2(hpa[1]);
    a0[0][0] = fmaf(x0, fa0.x, a0[0][0]); a0[0][1] = fmaf(x0, fa0.y, a0[0][1]);
    a0[0][2] = fmaf(x0, fa1.x, a0[0][2]); a0[0][3] = fmaf(x0, fa1.y, a0[0][3]);
    a0[1][0] = fmaf(x1, fa0.x, a0[1][0]); a0[1][1] = fmaf(x1, fa0.y, a0[1][1]);
    a0[1][2] = fmaf(x1, fa1.x, a0[1][2]); a0[1][3] = fmaf(x1, fa1.y, a0[1][3]);
    if (lane < 16) {
      float2 hwb = W2[k * 48 + 32 + lane];
      const __half2* hpb = reinterpret_cast<const __half2*>(&hwb);
      float2 fb0 = __half22float2(hpb[0]);
      float2 fb1 = __half22float2(hpb[1]);
      a1[0][0] = fmaf(x0, fb0.x, a1[0][0]); a1[0][1] = fmaf(x0, fb0.y, a1[0][1]);
      a1[0][2] = fmaf(x0, fb1.x, a1[0][2]); a1[0][3] = fmaf(x0, fb1.y, a1[0][3]);
      a1[1][0] = fmaf(x1, fb0.x, a1[1][0]); a1[1][1] = fmaf(x1, fb0.y, a1[1][1]);
      a1[1][2] = fmaf(x1, fb1.x, a1[1][2]); a1[1][3] = fmaf(x1, fb1.y, a1[1][3]);
    }
  }
#pragma unroll
  for (int row = 0; row < 2; ++row) {
    float4* P4 = reinterpret_cast<float4*>(part + (row * 8 + wg) * 192);
    P4[lane] = make_float4(a0[row][0], a0[row][1], a0[row][2], a0[row][3]);
    if (lane < 16)
      P4[32 + lane] = make_float4(a1[row][0], a1[row][1], a1[row][2], a1[row][3]);
  }
}

__device__ __forceinline__ float csum_hh8(const float* __restrict__ p,
                                          int row, int j) {
  const float* q = p + row * 8 * 192 + j;
  float a = q[0]        + q[192];
  float b = q[2 * 192]  + q[3 * 192];
  float c = q[4 * 192]  + q[5 * 192];
  float d = q[6 * 192]  + q[7 * 192];
  return (a + b) + (c + d);
}

// ---------------------------------------------------------------------------
// conditioning net (unchanged)
__device__ __forceinline__ void gemv_part(const float* __restrict__ Wt,
                                          const float* __restrict__ xs,
                                          int K, int N, float* part) {
  const int tid = threadIdx.x;
  const int kc  = tid >> 6;
  const int g0  = tid & 63;
  const int Kc  = K >> 2;
  const int G   = N >> 2;
  const float4* __restrict__ W4 = reinterpret_cast<const float4*>(Wt) + (size_t)(kc * Kc) * G;
  const float*  __restrict__ xk = xs + kc * Kc;
  float4* P4 = reinterpret_cast<float4*>(part + kc * N);
  for (int g = g0; g < G; g += 64) {
    float4 acc = make_float4(0.f, 0.f, 0.f, 0.f);
    const float4* wp = W4 + g;
#pragma unroll 4
    for (int k = 0; k < Kc; ++k) {
      const float xv = xk[k];
      const float4 w = wp[(size_t)k * G];
      acc.x = fmaf(xv, w.x, acc.x);
      acc.y = fmaf(xv, w.y, acc.y);
      acc.z = fmaf(xv, w.z, acc.z);
      acc.w = fmaf(xv, w.w, acc.w);
    }
    P4[g] = acc;
  }
}
__device__ __forceinline__ float csum4(const float* part, int N, int j) {
  return (part[j] + part[N + j]) + (part[2 * N + j] + part[3 * N + j]);
}

__global__ __launch_bounds__(256)
void cond_kernel(const float* __restrict__ feat, const float* __restrict__ gf) {
  __shared__ __align__(16) float s_part[4 * 512];
  __shared__ float s_x[336];
  __shared__ float s_y[336];
  const int b = blockIdx.x, f = blockIdx.y, tid = threadIdx.x;

  for (int j = tid; j < 80; j += 256)  s_x[j]      = feat[(b * 80 + j) * NFRAMES + f];
  for (int j = tid; j < 256; j += 256) s_x[80 + j] = gf[b * 256 + j];
  __syncthreads();
  gemv_part(g_wc + OFFC_C1, s_x, 336, 336, s_part);
  __syncthreads();
  for (int j = tid; j < 336; j += 256) s_y[j] = tanhf(csum4(s_part, 336, j));
  __syncthreads();
  gemv_part(g_wc + OFFC_C2, s_y, 336, 336, s_part);
  __syncthreads();
  for (int j = tid; j < 336; j += 256) s_x[j] = tanhf(csum4(s_part, 336, j));
  __syncthreads();
  gemv_part(g_wc + OFFC_C3, s_x, 336, 512, s_part);
  __syncthreads();
  float* dst = g_cond + (f * NB + b) * 512;
  for (int j = tid; j < 512; j += 256) dst[j] = tanhf(csum4(s_part, 512, j));
}

// ---------------------------------------------------------------------------
// main kernel: 32 clusters of 4 CTAs; cluster q handles rows 2q, 2q+1.
// dynamic smem: PART = 2*32*256 floats (64 KB); phase-A sub-buffers inside.
extern __shared__ float s_dyn[];
#define PART  (s_dyn)
#define P_FW  (PART)                   // 2*8*64  = 1024 floats
#define P_HH1 (PART + 1024)            // 2*8*192 = 3072 floats
#define P_HH2 (PART + 4096)
#define P_HH3 (PART + 7168)            // ends 10240 <= 16384

__global__ __launch_bounds__(NTHREADS, 1) __cluster_dims__(4, 1, 1)
void main_kernel(const float* __restrict__ prev0,
                 const int*   __restrict__ periods,
                 const float* __restrict__ gain_w,
                 const float* __restrict__ gain_b,
                 const float* __restrict__ pg_w,
                 const float* __restrict__ pg_b,
                 const float* __restrict__ out_w,
                 float*       __restrict__ outp) {
  __shared__ float s_x[2 * 1152];
  __shared__ __align__(16) float s_xg[2 * 192];
  __shared__ __align__(16) float s_hg1[2 * 192];
  __shared__ __align__(16) float s_hg2[2 * 192];
  __shared__ __align__(16) float s_hg3[2 * 192];
  __shared__ float s_prev[2 * 256], s_s1[2 * 256], s_s2[2 * 256], s_s3[2 * 256];
  __shared__ float s_s4[2 * 260];
  __shared__ float s_fw[2 * 256], s_fw2[2 * 256];
  __shared__ float s_o1[2 * 256], s_o2[2 * 256], s_o3[2 * 256];
  __shared__ float s_sk[2 * 256], s_sk2[2 * 256];
  __shared__ float s_pl[2 * 68], s_psub[2 * 64], s_pg[2 * 4], s_gain[2 * 2];
  __shared__ float s_out[2 * 64];

  const int tid  = threadIdx.x;
  const int rank = blockIdx.x & 3;
  const int q    = blockIdx.x >> 2;

  auto exch = [&](float* addr, float v) {
    *addr = v;
    uint32_t a = s2u_(addr);
    st_peer_(mapa_u_(a, (rank + 1) & 3), v);
    st_peer_(mapa_u_(a, (rank + 2) & 3), v);
    st_peer_(mapa_u_(a, (rank + 3) & 3), v);
  };

  if (tid < 512) {
    s_prev[tid] = prev0[q * 512 + tid];
    s_s1[tid] = 0.f; s_s2[tid] = 0.f; s_s3[tid] = 0.f;
  }
  if (tid < 520) s_s4[tid] = 0.f;
  __syncthreads();

  const float gb0 = gain_b[0];
  int per[2];
  const float* condr[2];

  for (int f = 0; f < NFRAMES; ++f) {
    per[0] = periods[(q * 2 + 0) * NFRAMES + f];
    per[1] = periods[(q * 2 + 1) * NFRAMES + f];
    condr[0] = g_cond + (f * NB + q * 2 + 0) * 512;
    condr[1] = g_cond + (f * NB + q * 2 + 1) * 512;

    for (int i = 0; i < 4; ++i) {
      // ---- gain: warp r computes row r
      if (tid < 64) {
        int row = tid >> 5, l = tid & 31;
        const float* sf = condr[row] + i * 128;
        float d = 0.f;
        for (int k = l; k < 128; k += 32) d = fmaf(sf[k], gain_w[k], d);
#pragma unroll
        for (int o = 16; o; o >>= 1) d += __shfl_xor_sync(0xffffffffu, d, o);
        if (l == 0) {
          float g = expf(d + gb0);
          s_gain[row * 2]     = g;
          s_gain[row * 2 + 1] = 1.0f / (1e-5f + g);
        }
      }
      __syncthreads();

      // ---- pitch gather + psub per row
      if (tid < 136) {
        int row = tid / 68, t = tid % 68;
        int idx = 256 - per[row] + t - 2;
        if (idx >= 256) idx -= per[row];
        s_pl[row * 68 + t] = s_prev[row * 256 + idx] * s_gain[row * 2 + 1];
      } else if (tid >= 256 && tid < 384) {
        int row = (tid - 256) >> 6, t = (tid - 256) & 63;
        s_psub[row * 64 + t] = s_prev[row * 256 + 192 + t] * s_gain[row * 2 + 1];
      }
      __syncthreads();

      // ---- fw input assembly
      for (int idx = tid; idx < 2 * 544; idx += NTHREADS) {
        int row = idx / 544, p = idx % 544;
        float v;
        if (p < 128)       v = condr[row][i * 128 + p];
        else if (p < 192)  v = s_psub[row * 64 + (p - 128)];
        else if (p < 260)  v = s_pl[row * 68 + (p - 192)];
        else if (p < 520)  v = s_s4[row * 260 + (p - 260)];
        else               v = 0.f;
        s_x[row * 1152 + p] = v;
      }
      __syncthreads();
      if (tid < 520) {
        int row = tid / 260, t = tid % 260;
        s_s4[row * 260 + t] = s_x[row * 1152 + t];
      }

      // ======= PHASE A: fw + HH1 + HH2 + HH3 on disjoint warp groups =======
      {
        const int w = tid >> 5;
        if (w < 8)       gemv_fw8(g_wh + OFFH_FW + rank * 544 * 64, s_x, 1152, P_FW);
        else if (w < 16) gemv_hh8(g_wh + OFFH_G1HH + rank * 256 * 192, s_s1, P_HH1);
        else if (w < 24) gemv_hh8(g_wh + OFFH_G2HH + rank * 256 * 192, s_s2, P_HH2);
        else             gemv_hh8(g_wh + OFFH_G3HH + rank * 256 * 192, s_s3, P_HH3);
      }
      __syncthreads();
      if (tid < 128) {
        int row = tid >> 6, jl = tid & 63;
        exch(&s_fw[row * 256 + rank * 64 + jl], tanhf(csum_fw8(P_FW, row, jl)));
      }
      for (int idx = tid; idx < 3 * 384; idx += NTHREADS) {
        int m = idx / 384, t = idx % 384;
        int row = t / 192, c = t % 192;
        float* dst = (m == 0) ? s_hg1 : (m == 1) ? s_hg2 : s_hg3;
        const float* src = (m == 0) ? P_HH1 : (m == 1) ? P_HH2 : P_HH3;
        dst[row * 192 + c] = csum_hh8(src, row, c);
      }
      CLUSTER_SYNC_();

      // ---- fwglu: redundant full-width, no exchange
      gemv2r<256, 256>(g_wh + OFFH_FWGLU, s_fw, 256, PART);
      __syncthreads();
      if (tid < 512) {
        int row = tid >> 8, j = tid & 255;
        s_fw2[row * 256 + j] =
            s_fw[row * 256 + j] * sigmoidf_(csum2r(PART, 256, row, j));
      }
      __syncthreads();

      // ---- pg: 8 warps (row, gate)
      if (tid < 256) {
        int w = tid >> 5, l = tid & 31;
        int row = w >> 2, g = w & 3;
        float d = 0.f;
        for (int k = l; k < 256; k += 32)
          d = fmaf(s_fw2[row * 256 + k], pg_w[g * 256 + k], d);
#pragma unroll
        for (int o = 16; o; o >>= 1) d += __shfl_xor_sync(0xffffffffu, d, o);
        if (l == 0) s_pg[row * 4 + g] = sigmoidf_(d + pg_b[g]) + 1e-5f;
      }
      __syncthreads();

      // ================= GRU (IH-only) + redundant GLU macros =================
#define GRU_STAGE(SRC, OFF_IH, HG, SSTATE, PGI)                                  \
      for (int idx = tid; idx < 2 * 384; idx += NTHREADS) {                      \
        int row = idx / 384, p = idx % 384;                                      \
        float v;                                                                 \
        if (p < 256)       v = SRC[row * 256 + p];                               \
        else if (p < 320)  v = s_pg[row * 4 + PGI] * s_pl[row * 68 + 2 + (p - 256)]; \
        else               v = s_psub[row * 64 + (p - 320)];                     \
        s_x[row * 1152 + p] = v;                                                 \
      }                                                                          \
      __syncthreads();                                                           \
      gemv2r<384, 192>(g_wh + OFF_IH + rank * 384 * 192, s_x, 1152, PART);       \
      __syncthreads();                                                           \
      if (tid < 96) {                                                            \
        int row = tid / 48, g4 = tid % 48;                                       \
        const float* p = PART + row * 32 * 192 + g4 * 4;                         \
        float4 u0 = make_float4(0.f, 0.f, 0.f, 0.f);                             \
        float4 u1 = make_float4(0.f, 0.f, 0.f, 0.f);                             \
        _Pragma("unroll")                                                        \
        for (int c = 0; c < 32; c += 2) {                                        \
          float4 va = *reinterpret_cast<const float4*>(p + c * 192);             \
          float4 vb = *reinterpret_cast<const float4*>(p + (c + 1) * 192);       \
          u0.x += va.x; u0.y += va.y; u0.z += va.z; u0.w += va.w;                \
          u1.x += vb.x; u1.y += vb.y; u1.z += vb.z; u1.w += vb.w;                \
        }                                                                        \
        float4 s = make_float4(u0.x + u1.x, u0.y + u1.y, u0.z + u1.z, u0.w + u1.w); \
        *reinterpret_cast<float4*>(s_xg + row * 192 + g4 * 4) = s;               \
      }                                                                          \
      __syncthreads();                                                           \
      if (tid < 128) {                                                           \
        int row = tid >> 6, sl = tid & 63;                                       \
        float r = sigmoidf_(s_xg[row * 192 + sl]       + HG[row * 192 + sl]);    \
        float z = sigmoidf_(s_xg[row * 192 + 64 + sl]  + HG[row * 192 + 64 + sl]); \
        float n = tanhf(s_xg[row * 192 + 128 + sl] + r * HG[row * 192 + 128 + sl]); \
        int j = rank * 64 + sl;                                                  \
        float v = (1.f - z) * n + z * SSTATE[row * 256 + j];                     \
        exch(&SSTATE[row * 256 + j], v);                                         \
      }                                                                          \
      CLUSTER_SYNC_();

#define GLU_STAGE(OFF_GLU, SSTATE, DST)                                          \
      gemv2r<256, 256>(g_wh + OFF_GLU, SSTATE, 256, PART);                       \
      __syncthreads();                                                           \
      if (tid < 512) {                                                           \
        int row = tid >> 8, j = tid & 255;                                       \
        DST[row * 256 + j] =                                                     \
            SSTATE[row * 256 + j] * sigmoidf_(csum2r(PART, 256, row, j));        \
      }                                                                          \
      __syncthreads();

      GRU_STAGE(s_fw2, OFFH_G1IH, s_hg1, s_s1, 0)
      GLU_STAGE(OFFH_GLU1, s_s1, s_o1)
      GRU_STAGE(s_o1, OFFH_G2IH, s_hg2, s_s2, 1)
      GLU_STAGE(OFFH_GLU2, s_s2, s_o2)
      GRU_STAGE(s_o2, OFFH_G3IH, s_hg3, s_s3, 2)
      GLU_STAGE(OFFH_GLU3, s_s3, s_o3)
#undef GRU_STAGE
#undef GLU_STAGE

      // ---- skip input: per row [o1,o2,o3,fw2,pg3*pl2,psub] = 1152
      for (int idx = tid; idx < 2 * 1152; idx += NTHREADS) {
        int row = idx / 1152, p = idx % 1152;
        float v;
        if (p < 256)        v = s_o1[row * 256 + p];
        else if (p < 512)   v = s_o2[row * 256 + (p - 256)];
        else if (p < 768)   v = s_o3[row * 256 + (p - 512)];
        else if (p < 1024)  v = s_fw2[row * 256 + (p - 768)];
        else if (p < 1088)  v = s_pg[row * 4 + 3] * s_pl[row * 68 + 2 + (p - 1024)];
        else                v = s_psub[row * 64 + (p - 1088)];
        s_x[row * 1152 + p] = v;
      }
      __syncthreads();
      gemv2r<1152, 64>(g_wh + OFFH_SKIP + rank * 1152 * 64, s_x, 1152, PART);
      __syncthreads();
      if (tid < 128) {
        int row = tid >> 6, jl = tid & 63;
        exch(&s_sk[row * 256 + rank * 64 + jl], tanhf(csum2r(PART, 64, row, jl)));
      }
      CLUSTER_SYNC_();

      // ---- skipglu: redundant full-width, no exchange
      gemv2r<256, 256>(g_wh + OFFH_SKIPGLU, s_sk, 256, PART);
      __syncthreads();
      if (tid < 512) {
        int row = tid >> 8, j = tid & 255;
        s_sk2[row * 256 + j] =
            s_sk[row * 256 + j] * sigmoidf_(csum2r(PART, 256, row, j));
      }
      __syncthreads();

      // ---- out: warp w -> output o = rank*16 + (w>>1), row = w&1
      {
        const int w = tid >> 5, l = tid & 31;
        const int o = rank * 16 + (w >> 1), row = w & 1;
        const float4* wr = reinterpret_cast<const float4*>(out_w + o * 256) + l * 2;
        const float4* xr = reinterpret_cast<const float4*>(s_sk2 + row * 256) + l * 2;
        float4 wa = wr[0], wb = wr[1];
        float4 xa = xr[0], xb = xr[1];
        float d = wa.x * xa.x + wa.y * xa.y + wa.z * xa.z + wa.w * xa.w
                + wb.x * xb.x + wb.y * xb.y + wb.z * xb.z + wb.w * xb.w;
#pragma unroll
        for (int oo = 16; oo; oo >>= 1) d += __shfl_xor_sync(0xffffffffu, d, oo);
        if (l == 0) {
          float v = tanhf(d) * s_gain[row * 2];
          exch(&s_out[row * 64 + o], v);
          outp[(q * 2 + row) * 25600 + f * 256 + i * 64 + o] = v;
        }
      }
      CLUSTER_SYNC_();

      // ---- prev = [prev[64:], out] per row
      float pv = 0.f;
      if (tid < 512) {
        int row = tid >> 8, t = tid & 255;
        pv = (t < 192) ? s_prev[row * 256 + t + 64] : s_out[row * 64 + (t - 192)];
      }
      __syncthreads();
      if (tid < 512) s_prev[tid] = pv;
      __syncthreads();
    }
  }
}

// ---------------------------------------------------------------------------
extern "C" void kernel_launch(void* const* d_in, const int* in_sizes, int n_in,
                              void* d_out, int out_size) {
  (void)in_sizes; (void)n_in; (void)out_size;
  const float* features = (const float*)d_in[0];
  const float* gfeat    = (const float*)d_in[1];
  const float* prev     = (const float*)d_in[2];
  const int*   periods  = (const int*)d_in[3];
  const float* cond_w1  = (const float*)d_in[4];
  const float* cond_w2  = (const float*)d_in[5];
  const float* cond_w3  = (const float*)d_in[6];
  const float* gain_w   = (const float*)d_in[7];
  const float* gain_b   = (const float*)d_in[8];
  const float* fw_w     = (const float*)d_in[9];
  const float* fw_glu_w = (const float*)d_in[10];
  const float* pg_w     = (const float*)d_in[11];
  const float* pg_b     = (const float*)d_in[12];
  const float* g1ih     = (const float*)d_in[13];
  const float* g1hh     = (const float*)d_in[14];
  const float* g2ih     = (const float*)d_in[15];
  const float* g2hh     = (const float*)d_in[16];
  const float* g3ih     = (const float*)d_in[17];
  const float* g3hh     = (const float*)d_in[18];
  const float* glu1     = (const float*)d_in[19];
  const float* glu2     = (const float*)d_in[20];
  const float* glu3     = (const float*)d_in[21];
  const float* skip_w   = (const float*)d_in[22];
  const float* skipglu  = (const float*)d_in[23];
  const float* out_w    = (const float*)d_in[24];

  __half* wh = nullptr;
  float*  wc = nullptr;
  cudaGetSymbolAddress((void**)&wh, g_wh);
  cudaGetSymbolAddress((void**)&wc, g_wc);

  auto rg4 = [&](const float* src, int off, int O, int I, int Ipad) {
    int tot = O * Ipad;
    reorg_h4<<<(tot + 255) / 256, 256>>>(src, wh + off, O, I, Ipad);
  };
  auto rgf = [&](const float* src, int off, int O, int I) {
    int tot = O * I;
    reorg_full<<<(tot + 255) / 256, 256>>>(src, wh + off, O, I);
  };
  auto rgg = [&](const float* src, int off, int I) {
    int tot = 768 * I;
    reorg_gru4<<<(tot + 255) / 256, 256>>>(src, wh + off, I);
  };
  auto tpc = [&](const float* src, int off, int O, int I) {
    int tot = O * I;
    transpose_k<<<(tot + 255) / 256, 256>>>(src, wc + off, O, I);
  };

  rg4(fw_w,     OFFH_FW,      256, 520, 544);
  rgf(fw_glu_w, OFFH_FWGLU,   256, 256);
  rgg(g1ih,     OFFH_G1IH,    384);
  rgg(g1hh,     OFFH_G1HH,    256);
  rgg(g2ih,     OFFH_G2IH,    384);
  rgg(g2hh,     OFFH_G2HH,    256);
  rgg(g3ih,     OFFH_G3IH,    384);
  rgg(g3hh,     OFFH_G3HH,    256);
  rgf(glu1,     OFFH_GLU1,    256, 256);
  rgf(glu2,     OFFH_GLU2,    256, 256);
  rgf(glu3,     OFFH_GLU3,    256, 256);
  rg4(skip_w,   OFFH_SKIP,    256, 1152, 1152);
  rgf(skipglu,  OFFH_SKIPGLU, 256, 256);
  tpc(cond_w1,  OFFC_C1,      336, 336);
  tpc(cond_w2,  OFFC_C2,      336, 336);
  tpc(cond_w3,  OFFC_C3,      512, 336);

  dim3 cg(NB, NFRAMES);
  cond_kernel<<<cg, 256>>>(features, gfeat);

  const int dyn_smem = 2 * 32 * 256 * (int)sizeof(float);  // 64 KB
  cudaFuncSetAttribute(main_kernel, cudaFuncAttributeMaxDynamicSharedMemorySize, dyn_smem);
  main_kernel<<<128, NTHREADS, dyn_smem>>>(prev, periods, gain_w, gain_b,
                                           pg_w, pg_b, out_w, (float*)d_out);
}

// round 16
// speedup vs baseline: 1.1115x; 1.1115x over previous
#include <cuda_runtime.h>
#include <cuda_fp16.h>
#include <stdint.h>
#include <math.h>

// ----------------------------------------------------------------------------
// FARGAN vocoder. Round 15: exact R13 main kernel (best: 13.58 ms) —
// 4-CTA clusters, 2 rows/cluster, 128 CTAs, HH-hoisted phase A.
// All 16 weight-reorg launches fused into ONE kernel so ncu's "-s 5 -c 1"
// lands on main_kernel next round (launch order: fused_reorg, cond, main).
// ----------------------------------------------------------------------------

#define NFRAMES 100
#define NB      64
#define NTHREADS 1024

__device__ __forceinline__ float sigmoidf_(float x) { return 1.0f / (1.0f + expf(-x)); }

__device__ __forceinline__ uint32_t s2u_(const void* p) {
  uint32_t a;
  asm("{ .reg .u64 t; cvta.to.shared.u64 t, %1; cvt.u32.u64 %0, t; }" : "=r"(a) : "l"(p));
  return a;
}
__device__ __forceinline__ uint32_t mapa_u_(uint32_t a, uint32_t r) {
  uint32_t d;
  asm("mapa.shared::cluster.u32 %0, %1, %2;" : "=r"(d) : "r"(a), "r"(r));
  return d;
}
__device__ __forceinline__ void st_peer_(uint32_t a, float v) {
  asm volatile("st.shared::cluster.f32 [%0], %1;" :: "r"(a), "f"(v));
}
#define CLUSTER_SYNC_() do { \
  asm volatile("barrier.cluster.arrive.aligned;" ::: "memory"); \
  asm volatile("barrier.cluster.wait.aligned;" ::: "memory"); \
} while (0)

// fp16 weights, 4 rank-slices per matrix: [4][Kpad][Oq]
enum : int {
  OFFH_FW      = 0,                          // 4 x 544 x 64
  OFFH_FWGLU   = OFFH_FW      + 544 * 256,   // 4 x 256 x 64
  OFFH_G1IH    = OFFH_FWGLU   + 256 * 256,   // 4 x 384 x 192
  OFFH_G1HH    = OFFH_G1IH    + 384 * 768,   // 4 x 256 x 192
  OFFH_G2IH    = OFFH_G1HH    + 256 * 768,
  OFFH_G2HH    = OFFH_G2IH    + 384 * 768,
  OFFH_G3IH    = OFFH_G2HH    + 256 * 768,
  OFFH_G3HH    = OFFH_G3IH    + 384 * 768,
  OFFH_GLU1    = OFFH_G3HH    + 256 * 768,
  OFFH_GLU2    = OFFH_GLU1    + 256 * 256,
  OFFH_GLU3    = OFFH_GLU2    + 256 * 256,
  OFFH_SKIP    = OFFH_GLU3    + 256 * 256,   // 4 x 1152 x 64
  OFFH_SKIPGLU = OFFH_SKIP    + 1152 * 256,
  WH_TOTAL     = OFFH_SKIPGLU + 256 * 256
};

enum : int {
  OFFC_C1  = 0,
  OFFC_C2  = OFFC_C1 + 336 * 336,
  OFFC_C3  = OFFC_C2 + 336 * 336,
  WC_TOTAL = OFFC_C3 + 336 * 512
};

__device__ __half g_wh[WH_TOTAL];
__device__ float  g_wc[WC_TOTAL];
__device__ float  g_cond[NFRAMES * NB * 512];

// ---------------------------------------------------------------------------
// fused reorg: one launch handles all 16 matrices (blockIdx.y selects).
__device__ __forceinline__ void rg4_(const float* __restrict__ src,
                                     __half* __restrict__ dst,
                                     int O, int I, int Ipad, int idx) {
  if (idx >= O * Ipad) return;
  int i = idx / O, o = idx % O;
  int Oq = O >> 2;
  int r = o / Oq, c = o % Oq;
  float v = (i < I) ? src[o * I + i] : 0.f;
  dst[((size_t)r * Ipad + i) * Oq + c] = __float2half(v);
}
__device__ __forceinline__ void rgg_(const float* __restrict__ src,
                                     __half* __restrict__ dst, int I, int idx) {
  if (idx >= 768 * I) return;
  int i = idx / 768, o = idx % 768;
  int s = o & 255, g = o >> 8;
  int r = s >> 6, c = g * 64 + (s & 63);
  dst[((size_t)r * I + i) * 192 + c] = __float2half(src[o * I + i]);
}
__device__ __forceinline__ void tpc_(const float* __restrict__ src,
                                     float* __restrict__ dst, int O, int I, int idx) {
  if (idx >= O * I) return;
  int i = idx / O, o = idx % O;
  dst[idx] = src[o * I + i];
}

__global__ void fused_reorg(
    const float* fw_w, const float* fw_glu_w,
    const float* g1ih, const float* g1hh,
    const float* g2ih, const float* g2hh,
    const float* g3ih, const float* g3hh,
    const float* glu1, const float* glu2, const float* glu3,
    const float* skip_w, const float* skipglu,
    const float* cw1, const float* cw2, const float* cw3) {
  const int idx = blockIdx.x * 256 + threadIdx.x;
  switch (blockIdx.y) {
    case 0:  rg4_(fw_w,     g_wh + OFFH_FW,      256, 520, 544, idx);  break;
    case 1:  rg4_(fw_glu_w, g_wh + OFFH_FWGLU,   256, 256, 256, idx);  break;
    case 2:  rgg_(g1ih,     g_wh + OFFH_G1IH,    384, idx);            break;
    case 3:  rgg_(g1hh,     g_wh + OFFH_G1HH,    256, idx);            break;
    case 4:  rgg_(g2ih,     g_wh + OFFH_G2IH,    384, idx);            break;
    case 5:  rgg_(g2hh,     g_wh + OFFH_G2HH,    256, idx);            break;
    case 6:  rgg_(g3ih,     g_wh + OFFH_G3IH,    384, idx);            break;
    case 7:  rgg_(g3hh,     g_wh + OFFH_G3HH,    256, idx);            break;
    case 8:  rg4_(glu1,     g_wh + OFFH_GLU1,    256, 256, 256, idx);  break;
    case 9:  rg4_(glu2,     g_wh + OFFH_GLU2,    256, 256, 256, idx);  break;
    case 10: rg4_(glu3,     g_wh + OFFH_GLU3,    256, 256, 256, idx);  break;
    case 11: rg4_(skip_w,   g_wh + OFFH_SKIP,    256, 1152, 1152, idx); break;
    case 12: rg4_(skipglu,  g_wh + OFFH_SKIPGLU, 256, 256, 256, idx);  break;
    case 13: tpc_(cw1,      g_wc + OFFC_C1,      336, 336, idx);       break;
    case 14: tpc_(cw2,      g_wc + OFFC_C2,      336, 336, idx);       break;
    default: tpc_(cw3,      g_wc + OFFC_C3,      512, 336, idx);       break;
  }
}

// ---------------------------------------------------------------------------
// 2-row fp16 GEMV partial, all 32 warps = 32 K-chunks x 32 lanes (R12/R13).
template <int K, int NQ>
__device__ __forceinline__ void gemv2r(const __half* __restrict__ Wh,
                                       const float* __restrict__ xs, int rs,
                                       float* __restrict__ part) {
  const int tid  = threadIdx.x;
  const int kc   = tid >> 5;
  const int lane = tid & 31;
  constexpr int Kc  = K / 32;
  constexpr int NV2 = NQ / 4;
  const float2* __restrict__ W2 =
      reinterpret_cast<const float2*>(Wh) + (size_t)(kc * Kc) * NV2;

  if (NQ == 64) {
    const int row = lane >> 4, v = lane & 15;
    const float* xk = xs + row * rs + kc * Kc;
    float acc[4] = {0.f, 0.f, 0.f, 0.f};
#pragma unroll 8
    for (int k = 0; k < Kc; ++k) {
      const float xv = xk[k];
      float2 hw = W2[k * 16 + v];
      const __half2* hp = reinterpret_cast<const __half2*>(&hw);
      float2 f0 = __half22float2(hp[0]);
      float2 f1 = __half22float2(hp[1]);
      acc[0] = fmaf(xv, f0.x, acc[0]);
      acc[1] = fmaf(xv, f0.y, acc[1]);
      acc[2] = fmaf(xv, f1.x, acc[2]);
      acc[3] = fmaf(xv, f1.y, acc[3]);
    }
    float4* P4 = reinterpret_cast<float4*>(part + (row * 32 + kc) * 64);
    P4[v] = make_float4(acc[0], acc[1], acc[2], acc[3]);
  } else {  // NQ == 192
    const float* xk0 = xs + kc * Kc;
    const float* xk1 = xs + rs + kc * Kc;
    float a0[2][4], a1[2][4];
#pragma unroll
    for (int j = 0; j < 4; ++j) { a0[0][j] = a0[1][j] = a1[0][j] = a1[1][j] = 0.f; }
#pragma unroll
    for (int k = 0; k < Kc; ++k) {
      const float x0 = xk0[k], x1 = xk1[k];
      float2 hwa = W2[k * 48 + lane];
      const __half2* hpa = reinterpret_cast<const __half2*>(&hwa);
      float2 fa0 = __half22float2(hpa[0]);
      float2 fa1 = __half22float2(hpa[1]);
      a0[0][0] = fmaf(x0, fa0.x, a0[0][0]); a0[0][1] = fmaf(x0, fa0.y, a0[0][1]);
      a0[0][2] = fmaf(x0, fa1.x, a0[0][2]); a0[0][3] = fmaf(x0, fa1.y, a0[0][3]);
      a0[1][0] = fmaf(x1, fa0.x, a0[1][0]); a0[1][1] = fmaf(x1, fa0.y, a0[1][1]);
      a0[1][2] = fmaf(x1, fa1.x, a0[1][2]); a0[1][3] = fmaf(x1, fa1.y, a0[1][3]);
      if (lane < 16) {
        float2 hwb = W2[k * 48 + 32 + lane];
        const __half2* hpb = reinterpret_cast<const __half2*>(&hwb);
        float2 fb0 = __half22float2(hpb[0]);
        float2 fb1 = __half22float2(hpb[1]);
        a1[0][0] = fmaf(x0, fb0.x, a1[0][0]); a1[0][1] = fmaf(x0, fb0.y, a1[0][1]);
        a1[0][2] = fmaf(x0, fb1.x, a1[0][2]); a1[0][3] = fmaf(x0, fb1.y, a1[0][3]);
        a1[1][0] = fmaf(x1, fb0.x, a1[1][0]); a1[1][1] = fmaf(x1, fb0.y, a1[1][1]);
        a1[1][2] = fmaf(x1, fb1.x, a1[1][2]); a1[1][3] = fmaf(x1, fb1.y, a1[1][3]);
      }
    }
#pragma unroll
    for (int row = 0; row < 2; ++row) {
      float4* P4 = reinterpret_cast<float4*>(part + (row * 32 + kc) * 192);
      P4[lane] = make_float4(a0[row][0], a0[row][1], a0[row][2], a0[row][3]);
      if (lane < 16)
        P4[32 + lane] = make_float4(a1[row][0], a1[row][1], a1[row][2], a1[row][3]);
    }
  }
}

__device__ __forceinline__ float csum2r(const float* __restrict__ part, int NQ,
                                        int row, int j) {
  const float* p = part + (row * 32) * NQ + j;
  float s = 0.f;
#pragma unroll
  for (int c = 0; c < 32; c += 4) {
    float a = p[c * NQ]       + p[(c + 1) * NQ];
    float b = p[(c + 2) * NQ] + p[(c + 3) * NQ];
    s += (a + b);
  }
  return s;
}

// ---------------------------------------------------------------------------
// Phase-A gemvs on 8-warp groups.
__device__ __forceinline__ void gemv_fw8(const __half* __restrict__ Wh,
                                         const float* __restrict__ xs, int rs,
                                         float* __restrict__ part) {
  const int w = threadIdx.x >> 5;
  const int lane = threadIdx.x & 31;
  const int row = lane >> 4, v = lane & 15;
  constexpr int Kc = 544 / 8;
  const float* xk = xs + row * rs + w * Kc;
  const float2* __restrict__ W2 =
      reinterpret_cast<const float2*>(Wh) + (size_t)(w * Kc) * 16 + v;
  float acc[4] = {0.f, 0.f, 0.f, 0.f};
#pragma unroll 8
  for (int k = 0; k < Kc; ++k) {
    const float xv = xk[k];
    float2 hw = W2[k * 16];
    const __half2* hp = reinterpret_cast<const __half2*>(&hw);
    float2 f0 = __half22float2(hp[0]);
    float2 f1 = __half22float2(hp[1]);
    acc[0] = fmaf(xv, f0.x, acc[0]);
    acc[1] = fmaf(xv, f0.y, acc[1]);
    acc[2] = fmaf(xv, f1.x, acc[2]);
    acc[3] = fmaf(xv, f1.y, acc[3]);
  }
  reinterpret_cast<float4*>(part + (row * 8 + w) * 64)[v] =
      make_float4(acc[0], acc[1], acc[2], acc[3]);
}

__device__ __forceinline__ float csum_fw8(const float* __restrict__ p,
                                          int row, int j) {
  const float* q = p + row * 8 * 64 + j;
  float a = q[0]       + q[64];
  float b = q[2 * 64]  + q[3 * 64];
  float c = q[4 * 64]  + q[5 * 64];
  float d = q[6 * 64]  + q[7 * 64];
  return (a + b) + (c + d);
}

__device__ __forceinline__ void gemv_hh8(const __half* __restrict__ Wh,
                                         const float* __restrict__ xs,
                                         float* __restrict__ part) {
  const int wg = (threadIdx.x >> 5) & 7;
  const int lane = threadIdx.x & 31;
  constexpr int Kc = 32;
  const float* xk0 = xs + wg * Kc;
  const float* xk1 = xs + 256 + wg * Kc;
  const float2* __restrict__ W2 =
      reinterpret_cast<const float2*>(Wh) + (size_t)(wg * Kc) * 48;

  float a0[2][4], a1[2][4];
#pragma unroll
  for (int j = 0; j < 4; ++j) { a0[0][j] = a0[1][j] = a1[0][j] = a1[1][j] = 0.f; }
#pragma unroll 4
  for (int k = 0; k < Kc; ++k) {
    const float x0 = xk0[k], x1 = xk1[k];
    float2 hwa = W2[k * 48 + lane];
    const __half2* hpa = reinterpret_cast<const __half2*>(&hwa);
    float2 fa0 = __half22float2(hpa[0]);
    float2 fa1 = __half22float2(hpa[1]);
    a0[0][0] = fmaf(x0, fa0.x, a0[0][0]); a0[0][1] = fmaf(x0, fa0.y, a0[0][1]);
    a0[0][2] = fmaf(x0, fa1.x, a0[0][2]); a0[0][3] = fmaf(x0, fa1.y, a0[0][3]);
    a0[1][0] = fmaf(x1, fa0.x, a0[1][0]); a0[1][1] = fmaf(x1, fa0.y, a0[1][1]);
    a0[1][2] = fmaf(x1, fa1.x, a0[1][2]); a0[1][3] = fmaf(x1, fa1.y, a0[1][3]);
    if (lane < 16) {
      float2 hwb = W2[k * 48 + 32 + lane];
      const __half2* hpb = reinterpret_cast<const __half2*>(&hwb);
      float2 fb0 = __half22float2(hpb[0]);
      float2 fb1 = __half22float2(hpb[1]);
      a1[0][0] = fmaf(x0, fb0.x, a1[0][0]); a1[0][1] = fmaf(x0, fb0.y, a1[0][1]);
      a1[0][2] = fmaf(x0, fb1.x, a1[0][2]); a1[0][3] = fmaf(x0, fb1.y, a1[0][3]);
      a1[1][0] = fmaf(x1, fb0.x, a1[1][0]); a1[1][1] = fmaf(x1, fb0.y, a1[1][1]);
      a1[1][2] = fmaf(x1, fb1.x, a1[1][2]); a1[1][3] = fmaf(x1, fb1.y, a1[1][3]);
    }
  }
#pragma unroll
  for (int row = 0; row < 2; ++row) {
    float4* P4 = reinterpret_cast<float4*>(part + (row * 8 + wg) * 192);
    P4[lane] = make_float4(a0[row][0], a0[row][1], a0[row][2], a0[row][3]);
    if (lane < 16)
      P4[32 + lane] = make_float4(a1[row][0], a1[row][1], a1[row][2], a1[row][3]);
  }
}

__device__ __forceinline__ float csum_hh8(const float* __restrict__ p,
                                          int row, int j) {
  const float* q = p + row * 8 * 192 + j;
  float a = q[0]        + q[192];
  float b = q[2 * 192]  + q[3 * 192];
  float c = q[4 * 192]  + q[5 * 192];
  float d = q[6 * 192]  + q[7 * 192];
  return (a + b) + (c + d);
}

// ---------------------------------------------------------------------------
// conditioning net
__device__ __forceinline__ void gemv_part(const float* __restrict__ Wt,
                                          const float* __restrict__ xs,
                                          int K, int N, float* part) {
  const int tid = threadIdx.x;
  const int kc  = tid >> 6;
  const int g0  = tid & 63;
  const int Kc  = K >> 2;
  const int G   = N >> 2;
  const float4* __restrict__ W4 = reinterpret_cast<const float4*>(Wt) + (size_t)(kc * Kc) * G;
  const float*  __restrict__ xk = xs + kc * Kc;
  float4* P4 = reinterpret_cast<float4*>(part + kc * N);
  for (int g = g0; g < G; g += 64) {
    float4 acc = make_float4(0.f, 0.f, 0.f, 0.f);
    const float4* wp = W4 + g;
#pragma unroll 4
    for (int k = 0; k < Kc; ++k) {
      const float xv = xk[k];
      const float4 w = wp[(size_t)k * G];
      acc.x = fmaf(xv, w.x, acc.x);
      acc.y = fmaf(xv, w.y, acc.y);
      acc.z = fmaf(xv, w.z, acc.z);
      acc.w = fmaf(xv, w.w, acc.w);
    }
    P4[g] = acc;
  }
}
__device__ __forceinline__ float csum4(const float* part, int N, int j) {
  return (part[j] + part[N + j]) + (part[2 * N + j] + part[3 * N + j]);
}

__global__ __launch_bounds__(256)
void cond_kernel(const float* __restrict__ feat, const float* __restrict__ gf) {
  __shared__ __align__(16) float s_part[4 * 512];
  __shared__ float s_x[336];
  __shared__ float s_y[336];
  const int b = blockIdx.x, f = blockIdx.y, tid = threadIdx.x;

  for (int j = tid; j < 80; j += 256)  s_x[j]      = feat[(b * 80 + j) * NFRAMES + f];
  for (int j = tid; j < 256; j += 256) s_x[80 + j] = gf[b * 256 + j];
  __syncthreads();
  gemv_part(g_wc + OFFC_C1, s_x, 336, 336, s_part);
  __syncthreads();
  for (int j = tid; j < 336; j += 256) s_y[j] = tanhf(csum4(s_part, 336, j));
  __syncthreads();
  gemv_part(g_wc + OFFC_C2, s_y, 336, 336, s_part);
  __syncthreads();
  for (int j = tid; j < 336; j += 256) s_x[j] = tanhf(csum4(s_part, 336, j));
  __syncthreads();
  gemv_part(g_wc + OFFC_C3, s_x, 336, 512, s_part);
  __syncthreads();
  float* dst = g_cond + (f * NB + b) * 512;
  for (int j = tid; j < 512; j += 256) dst[j] = tanhf(csum4(s_part, 512, j));
}

// ---------------------------------------------------------------------------
// main kernel: 32 clusters of 4 CTAs; cluster q handles rows 2q, 2q+1.
extern __shared__ float s_dyn[];
#define PART_A (s_dyn)
#define PART_B (s_dyn + 2 * 32 * 192)
#define P_FW  (PART_A)                 // 2*8*64  = 1024 floats
#define P_HH1 (PART_A + 1024)          // 2*8*192 = 3072 floats
#define P_HH2 (PART_A + 4096)
#define P_HH3 (PART_A + 7168)          // ends at 10240 < 12288

__global__ __launch_bounds__(NTHREADS, 1) __cluster_dims__(4, 1, 1)
void main_kernel(const float* __restrict__ prev0,
                 const int*   __restrict__ periods,
                 const float* __restrict__ gain_w,
                 const float* __restrict__ gain_b,
                 const float* __restrict__ pg_w,
                 const float* __restrict__ pg_b,
                 const float* __restrict__ out_w,
                 float*       __restrict__ outp) {
  __shared__ float s_x[2 * 1152];
  __shared__ __align__(16) float s_xg[2 * 192];
  __shared__ __align__(16) float s_hg1[2 * 192];
  __shared__ __align__(16) float s_hg2[2 * 192];
  __shared__ __align__(16) float s_hg3[2 * 192];
  __shared__ float s_prev[2 * 256], s_s1[2 * 256], s_s2[2 * 256], s_s3[2 * 256];
  __shared__ float s_s4[2 * 260];
  __shared__ float s_fw[2 * 256], s_fw2[2 * 256];
  __shared__ float s_o1[2 * 256], s_o2[2 * 256], s_o3[2 * 256];
  __shared__ float s_sk[2 * 256], s_sk2[2 * 256];
  __shared__ float s_pl[2 * 68], s_psub[2 * 64], s_pg[2 * 4], s_gain[2 * 2];
  __shared__ float s_out[2 * 64];

  const int tid  = threadIdx.x;
  const int rank = blockIdx.x & 3;
  const int q    = blockIdx.x >> 2;

  auto exch = [&](float* addr, float v) {
    *addr = v;
    uint32_t a = s2u_(addr);
    st_peer_(mapa_u_(a, (rank + 1) & 3), v);
    st_peer_(mapa_u_(a, (rank + 2) & 3), v);
    st_peer_(mapa_u_(a, (rank + 3) & 3), v);
  };

  if (tid < 512) {
    s_prev[tid] = prev0[q * 512 + tid];
    s_s1[tid] = 0.f; s_s2[tid] = 0.f; s_s3[tid] = 0.f;
  }
  if (tid < 520) s_s4[tid] = 0.f;
  __syncthreads();

  const float gb0 = gain_b[0];
  int per[2];
  const float* condr[2];

  for (int f = 0; f < NFRAMES; ++f) {
    per[0] = periods[(q * 2 + 0) * NFRAMES + f];
    per[1] = periods[(q * 2 + 1) * NFRAMES + f];
    condr[0] = g_cond + (f * NB + q * 2 + 0) * 512;
    condr[1] = g_cond + (f * NB + q * 2 + 1) * 512;

    for (int i = 0; i < 4; ++i) {
      // ---- gain: warp r computes row r
      if (tid < 64) {
        int row = tid >> 5, l = tid & 31;
        const float* sf = condr[row] + i * 128;
        float d = 0.f;
        for (int k = l; k < 128; k += 32) d = fmaf(sf[k], gain_w[k], d);
#pragma unroll
        for (int o = 16; o; o >>= 1) d += __shfl_xor_sync(0xffffffffu, d, o);
        if (l == 0) {
          float g = expf(d + gb0);
          s_gain[row * 2]     = g;
          s_gain[row * 2 + 1] = 1.0f / (1e-5f + g);
        }
      }
      __syncthreads();

      // ---- pitch gather + psub per row
      if (tid < 136) {
        int row = tid / 68, t = tid % 68;
        int idx = 256 - per[row] + t - 2;
        if (idx >= 256) idx -= per[row];
        s_pl[row * 68 + t] = s_prev[row * 256 + idx] * s_gain[row * 2 + 1];
      } else if (tid >= 256 && tid < 384) {
        int row = (tid - 256) >> 6, t = (tid - 256) & 63;
        s_psub[row * 64 + t] = s_prev[row * 256 + 192 + t] * s_gain[row * 2 + 1];
      }
      __syncthreads();

      // ---- fw input assembly: per row [sf(128), psub(64), pl(68), s4(260), pad]
      for (int idx = tid; idx < 2 * 544; idx += NTHREADS) {
        int row = idx / 544, p = idx % 544;
        float v;
        if (p < 128)       v = condr[row][i * 128 + p];
        else if (p < 192)  v = s_psub[row * 64 + (p - 128)];
        else if (p < 260)  v = s_pl[row * 68 + (p - 192)];
        else if (p < 520)  v = s_s4[row * 260 + (p - 260)];
        else               v = 0.f;
        s_x[row * 1152 + p] = v;
      }
      __syncthreads();
      if (tid < 520) {
        int row = tid / 260, t = tid % 260;
        s_s4[row * 260 + t] = s_x[row * 1152 + t];
      }

      // ======= PHASE A: fw + HH1 + HH2 + HH3 on disjoint warp groups =======
      {
        const int w = tid >> 5;
        if (w < 8)       gemv_fw8(g_wh + OFFH_FW + rank * 544 * 64, s_x, 1152, P_FW);
        else if (w < 16) gemv_hh8(g_wh + OFFH_G1HH + rank * 256 * 192, s_s1, P_HH1);
        else if (w < 24) gemv_hh8(g_wh + OFFH_G2HH + rank * 256 * 192, s_s2, P_HH2);
        else             gemv_hh8(g_wh + OFFH_G3HH + rank * 256 * 192, s_s3, P_HH3);
      }
      __syncthreads();
      if (tid < 128) {
        int row = tid >> 6, jl = tid & 63;
        exch(&s_fw[row * 256 + rank * 64 + jl], tanhf(csum_fw8(P_FW, row, jl)));
      }
      for (int idx = tid; idx < 3 * 384; idx += NTHREADS) {
        int m = idx / 384, t = idx % 384;
        int row = t / 192, c = t % 192;
        float* dst = (m == 0) ? s_hg1 : (m == 1) ? s_hg2 : s_hg3;
        const float* src = (m == 0) ? P_HH1 : (m == 1) ? P_HH2 : P_HH3;
        dst[row * 192 + c] = csum_hh8(src, row, c);
      }
      CLUSTER_SYNC_();

      gemv2r<256, 64>(g_wh + OFFH_FWGLU + rank * 256 * 64, s_fw, 256, PART_A);
      __syncthreads();
      if (tid < 128) {
        int row = tid >> 6, jl = tid & 63;
        int j = rank * 64 + jl;
        float v = s_fw[row * 256 + j] * sigmoidf_(csum2r(PART_A, 64, row, jl));
        exch(&s_fw2[row * 256 + j], v);
      }
      CLUSTER_SYNC_();

      // ---- pg: 8 warps (row, gate)
      if (tid < 256) {
        int w = tid >> 5, l = tid & 31;
        int row = w >> 2, g = w & 3;
        float d = 0.f;
        for (int k = l; k < 256; k += 32)
          d = fmaf(s_fw2[row * 256 + k], pg_w[g * 256 + k], d);
#pragma unroll
        for (int o = 16; o; o >>= 1) d += __shfl_xor_sync(0xffffffffu, d, o);
        if (l == 0) s_pg[row * 4 + g] = sigmoidf_(d + pg_b[g]) + 1e-5f;
      }
      __syncthreads();

      // ================= GRU (IH-only) + GLU macros =================
#define GRU_STAGE(SRC, OFF_IH, HG, SSTATE, PGI)                                  \
      for (int idx = tid; idx < 2 * 384; idx += NTHREADS) {                      \
        int row = idx / 384, p = idx % 384;                                      \
        float v;                                                                 \
        if (p < 256)       v = SRC[row * 256 + p];                               \
        else if (p < 320)  v = s_pg[row * 4 + PGI] * s_pl[row * 68 + 2 + (p - 256)]; \
        else               v = s_psub[row * 64 + (p - 320)];                     \
        s_x[row * 1152 + p] = v;                                                 \
      }                                                                          \
      __syncthreads();                                                           \
      gemv2r<384, 192>(g_wh + OFF_IH + rank * 384 * 192, s_x, 1152, PART_A);     \
      __syncthreads();                                                           \
      if (tid < 96) {                                                            \
        int row = tid / 48, g4 = tid % 48;                                       \
        const float* p = PART_A + row * 32 * 192 + g4 * 4;                       \
        float4 u0 = make_float4(0.f, 0.f, 0.f, 0.f);                             \
        float4 u1 = make_float4(0.f, 0.f, 0.f, 0.f);                             \
        _Pragma("unroll")                                                        \
        for (int c = 0; c < 32; c += 2) {                                        \
          float4 va = *reinterpret_cast<const float4*>(p + c * 192);             \
          float4 vb = *reinterpret_cast<const float4*>(p + (c + 1) * 192);       \
          u0.x += va.x; u0.y += va.y; u0.z += va.z; u0.w += va.w;                \
          u1.x += vb.x; u1.y += vb.y; u1.z += vb.z; u1.w += vb.w;                \
        }                                                                        \
        float4 s = make_float4(u0.x + u1.x, u0.y + u1.y, u0.z + u1.z, u0.w + u1.w); \
        *reinterpret_cast<float4*>(s_xg + row * 192 + g4 * 4) = s;               \
      }                                                                          \
      __syncthreads();                                                           \
      if (tid < 128) {                                                           \
        int row = tid >> 6, sl = tid & 63;                                       \
        float r = sigmoidf_(s_xg[row * 192 + sl]       + HG[row * 192 + sl]);    \
        float z = sigmoidf_(s_xg[row * 192 + 64 + sl]  + HG[row * 192 + 64 + sl]); \
        float n = tanhf(s_xg[row * 192 + 128 + sl] + r * HG[row * 192 + 128 + sl]); \
        int j = rank * 64 + sl;                                                  \
        float v = (1.f - z) * n + z * SSTATE[row * 256 + j];                     \
        exch(&SSTATE[row * 256 + j], v);                                         \
      }                                                                          \
      CLUSTER_SYNC_();

#define GLU_STAGE(OFF_GLU, SSTATE, DST)                                          \
      gemv2r<256, 64>(g_wh + OFF_GLU + rank * 256 * 64, SSTATE, 256, PART_A);    \
      __syncthreads();                                                           \
      if (tid < 128) {                                                           \
        int row = tid >> 6, jl = tid & 63;                                       \
        int j = rank * 64 + jl;                                                  \
        float v = SSTATE[row * 256 + j] * sigmoidf_(csum2r(PART_A, 64, row, jl)); \
        exch(&DST[row * 256 + j], v);                                            \
      }                                                                          \
      CLUSTER_SYNC_();

      GRU_STAGE(s_fw2, OFFH_G1IH, s_hg1, s_s1, 0)
      GLU_STAGE(OFFH_GLU1, s_s1, s_o1)
      GRU_STAGE(s_o1, OFFH_G2IH, s_hg2, s_s2, 1)
      GLU_STAGE(OFFH_GLU2, s_s2, s_o2)
      GRU_STAGE(s_o2, OFFH_G3IH, s_hg3, s_s3, 2)
      GLU_STAGE(OFFH_GLU3, s_s3, s_o3)
#undef GRU_STAGE
#undef GLU_STAGE

      // ---- skip input: per row [o1,o2,o3,fw2,pg3*pl2,psub] = 1152
      for (int idx = tid; idx < 2 * 1152; idx += NTHREADS) {
        int row = idx / 1152, p = idx % 1152;
        float v;
        if (p < 256)        v = s_o1[row * 256 + p];
        else if (p < 512)   v = s_o2[row * 256 + (p - 256)];
        else if (p < 768)   v = s_o3[row * 256 + (p - 512)];
        else if (p < 1024)  v = s_fw2[row * 256 + (p - 768)];
        else if (p < 1088)  v = s_pg[row * 4 + 3] * s_pl[row * 68 + 2 + (p - 1024)];
        else                v = s_psub[row * 64 + (p - 1088)];
        s_x[row * 1152 + p] = v;
      }
      __syncthreads();
      gemv2r<1152, 64>(g_wh + OFFH_SKIP + rank * 1152 * 64, s_x, 1152, PART_A);
      __syncthreads();
      if (tid < 128) {
        int row = tid >> 6, jl = tid & 63;
        exch(&s_sk[row * 256 + rank * 64 + jl], tanhf(csum2r(PART_A, 64, row, jl)));
      }
      CLUSTER_SYNC_();

      gemv2r<256, 64>(g_wh + OFFH_SKIPGLU + rank * 256 * 64, s_sk, 256, PART_A);
      __syncthreads();
      if (tid < 128) {
        int row = tid >> 6, jl = tid & 63;
        int j = rank * 64 + jl;
        float v = s_sk[row * 256 + j] * sigmoidf_(csum2r(PART_A, 64, row, jl));
        exch(&s_sk2[row * 256 + j], v);
      }
      CLUSTER_SYNC_();

      // ---- out: warp w -> output o = rank*16 + (w>>1), row = w&1
      {
        const int w = tid >> 5, l = tid & 31;
        const int o = rank * 16 + (w >> 1), row = w & 1;
        const float4* wr = reinterpret_cast<const float4*>(out_w + o * 256) + l * 2;
        const float4* xr = reinterpret_cast<const float4*>(s_sk2 + row * 256) + l * 2;
        float4 wa = wr[0], wb = wr[1];
        float4 xa = xr[0], xb = xr[1];
        float d = wa.x * xa.x + wa.y * xa.y + wa.z * xa.z + wa.w * xa.w
                + wb.x * xb.x + wb.y * xb.y + wb.z * xb.z + wb.w * xb.w;
#pragma unroll
        for (int oo = 16; oo; oo >>= 1) d += __shfl_xor_sync(0xffffffffu, d, oo);
        if (l == 0) {
          float v = tanhf(d) * s_gain[row * 2];
          exch(&s_out[row * 64 + o], v);
          outp[(q * 2 + row) * 25600 + f * 256 + i * 64 + o] = v;
        }
      }
      CLUSTER_SYNC_();

      // ---- prev = [prev[64:], out] per row
      float pv = 0.f;
      if (tid < 512) {
        int row = tid >> 8, t = tid & 255;
        pv = (t < 192) ? s_prev[row * 256 + t + 64] : s_out[row * 64 + (t - 192)];
      }
      __syncthreads();
      if (tid < 512) s_prev[tid] = pv;
      __syncthreads();
    }
  }
}

// ---------------------------------------------------------------------------
extern "C" void kernel_launch(void* const* d_in, const int* in_sizes, int n_in,
                              void* d_out, int out_size) {
  (void)in_sizes; (void)n_in; (void)out_size;
  const float* features = (const float*)d_in[0];
  const float* gfeat    = (const float*)d_in[1];
  const float* prev     = (const float*)d_in[2];
  const int*   periods  = (const int*)d_in[3];
  const float* cond_w1  = (const float*)d_in[4];
  const float* cond_w2  = (const float*)d_in[5];
  const float* cond_w3  = (const float*)d_in[6];
  const float* gain_w   = (const float*)d_in[7];
  const float* gain_b   = (const float*)d_in[8];
  const float* fw_w     = (const float*)d_in[9];
  const float* fw_glu_w = (const float*)d_in[10];
  const float* pg_w     = (const float*)d_in[11];
  const float* pg_b     = (const float*)d_in[12];
  const float* g1ih     = (const float*)d_in[13];
  const float* g1hh     = (const float*)d_in[14];
  const float* g2ih     = (const float*)d_in[15];
  const float* g2hh     = (const float*)d_in[16];
  const float* g3ih     = (const float*)d_in[17];
  const float* g3hh     = (const float*)d_in[18];
  const float* glu1     = (const float*)d_in[19];
  const float* glu2     = (const float*)d_in[20];
  const float* glu3     = (const float*)d_in[21];
  const float* skip_w   = (const float*)d_in[22];
  const float* skipglu  = (const float*)d_in[23];
  const float* out_w    = (const float*)d_in[24];

  // one fused reorg launch covering all 16 matrices (max elems 1152*256)
  dim3 rg(1152, 16);
  fused_reorg<<<rg, 256>>>(fw_w, fw_glu_w, g1ih, g1hh, g2ih, g2hh, g3ih, g3hh,
                           glu1, glu2, glu3, skip_w, skipglu,
                           cond_w1, cond_w2, cond_w3);

  dim3 cg(NB, NFRAMES);
  cond_kernel<<<cg, 256>>>(features, gfeat);

  const int dyn_smem = 2 * 2 * 32 * 192 * (int)sizeof(float);  // 96 KB
  cudaFuncSetAttribute(main_kernel, cudaFuncAttributeMaxDynamicSharedMemorySize, dyn_smem);
  main_kernel<<<128, NTHREADS, dyn_smem>>>(prev, periods, gain_w, gain_b,
                                           pg_w, pg_b, out_w, (float*)d_out);
}